// round 1
// baseline (speedup 1.0000x reference)
#include <cuda_runtime.h>
#include <cstdint>

// Problem constants (from reference): BS=1048576, N_HIDDEN=64, N_CLUSTERS=64, ALPHA=1
#define NH 64
#define NK 64
#define ROWS 256   // threads per block == rows per block

__device__ float g_c2[NK];
__device__ float g_colsum[NK];

// ---------------------------------------------------------------------------
// K0: precompute ||c_k||^2 and zero the column-sum accumulator (every launch,
// so graph replays are deterministic).
// ---------------------------------------------------------------------------
__global__ void k_pre(const float* __restrict__ c) {
    int k = threadIdx.x;
    if (k < NK) {
        float s = 0.f;
#pragma unroll
        for (int h = 0; h < NH; ++h) {
            float v = c[k * NH + h];
            s = fmaf(v, v, s);
        }
        g_c2[k] = s;
        g_colsum[k] = 0.f;
    }
}

// ---------------------------------------------------------------------------
// K1: per-row Q computation. One thread per row. Centroids transposed into
// shared; rank-1 inner loop with packed fp32x2 FMAs (Blackwell f32x2 pipe).
// Writes normalized Q and accumulates column sums (warp-shuffle reduce ->
// shared -> one global atomic per column per block).
// ---------------------------------------------------------------------------
__global__ void __launch_bounds__(ROWS) k_pass1(const float* __restrict__ z,
                                                const float* __restrict__ c,
                                                float* __restrict__ Q) {
    __shared__ __align__(16) float cs[NH * NK];  // cs[h*NK + k] = c[k][h]
    __shared__ float s_c2[NK];
    __shared__ float s_col[NK];

    const int t = threadIdx.x;

    // Load centroids transposed (one-time; store conflicts irrelevant).
    for (int i = t; i < NH * NK; i += ROWS) {
        int k = i / NH;
        int h = i % NH;
        cs[h * NK + k] = c[i];
    }
    if (t < NK) {
        s_c2[t] = g_c2[t];
        s_col[t] = 0.f;
    }
    __syncthreads();

    const long long b = (long long)blockIdx.x * ROWS + t;
    const float4* __restrict__ zr = (const float4*)(z + b * (long long)NH);

    // Packed accumulators: acc[i] holds (dot_{2i}, dot_{2i+1}) as two f32.
    unsigned long long acc[NK / 2];
#pragma unroll
    for (int i = 0; i < NK / 2; ++i) acc[i] = 0ULL;

    float z2 = 0.f;

#pragma unroll
    for (int h4 = 0; h4 < NH / 4; ++h4) {
        float4 zv = zr[h4];
        z2 = fmaf(zv.x, zv.x, z2);
        z2 = fmaf(zv.y, zv.y, z2);
        z2 = fmaf(zv.z, zv.z, z2);
        z2 = fmaf(zv.w, zv.w, z2);
        float zh[4] = {zv.x, zv.y, zv.z, zv.w};
#pragma unroll
        for (int j = 0; j < 4; ++j) {
            unsigned long long zz;
            asm("mov.b64 %0, {%1, %1};" : "=l"(zz) : "f"(zh[j]));
            const ulonglong2* cp =
                (const ulonglong2*)(cs + (h4 * 4 + j) * NK);
#pragma unroll
            for (int kk = 0; kk < NK / 4; ++kk) {
                ulonglong2 cv = cp[kk];  // broadcast LDS.128 (uniform addr)
                asm("fma.rn.f32x2 %0, %1, %2, %0;"
                    : "+l"(acc[2 * kk]) : "l"(zz), "l"(cv.x));
                asm("fma.rn.f32x2 %0, %1, %2, %0;"
                    : "+l"(acc[2 * kk + 1]) : "l"(zz), "l"(cv.y));
            }
        }
    }

    // Epilogue: d2 -> sim -> q_raw, row sum, normalize.
    float q[NK];
    float rowsum = 0.f;
#pragma unroll
    for (int i = 0; i < NK / 2; ++i) {
        float d0, d1;
        asm("mov.b64 {%0, %1}, %2;" : "=f"(d0), "=f"(d1) : "l"(acc[i]));
        int k0 = 2 * i;
        float da = fmaf(-2.f, d0, z2 + s_c2[k0]);
        float db = fmaf(-2.f, d1, z2 + s_c2[k0 + 1]);
        float s0 = sqrtf(fmaxf(da, 0.f));
        float s1 = sqrtf(fmaxf(db, 0.f));
        float q0 = 1.f / (1.f + s0);   // ALPHA=1: (1+sim)^-1
        float q1 = 1.f / (1.f + s1);
        q[k0] = q0;
        q[k0 + 1] = q1;
        rowsum += q0 + q1;
    }
    const float inv = 1.f / rowsum;
#pragma unroll
    for (int k = 0; k < NK; ++k) q[k] *= inv;

    // Write normalized Q row (contiguous 256B per thread, float4 stores).
    float4* __restrict__ qo = (float4*)(Q + b * (long long)NH);
#pragma unroll
    for (int k4 = 0; k4 < NK / 4; ++k4) {
        float4 v;
        v.x = q[4 * k4 + 0];
        v.y = q[4 * k4 + 1];
        v.z = q[4 * k4 + 2];
        v.w = q[4 * k4 + 3];
        qo[k4] = v;
    }

    // Column sums: warp-shuffle reduce per column, lane0 -> shared atomic.
#pragma unroll
    for (int k = 0; k < NK; ++k) {
        float v = q[k];
#pragma unroll
        for (int off = 16; off > 0; off >>= 1)
            v += __shfl_xor_sync(0xffffffffu, v, off);
        if ((t & 31) == 0) atomicAdd(&s_col[k], v);
    }
    __syncthreads();
    if (t < NK) atomicAdd(&g_colsum[t], s_col[t]);
}

// ---------------------------------------------------------------------------
// K2: P = (Q*Q / colsum) row-normalized. Memory-bound streaming pass.
// ---------------------------------------------------------------------------
__global__ void __launch_bounds__(ROWS) k_pass2(const float* __restrict__ Q,
                                                float* __restrict__ P) {
    __shared__ float s_ic[NK];
    const int t = threadIdx.x;
    if (t < NK) s_ic[t] = 1.f / g_colsum[t];
    __syncthreads();

    const long long b = (long long)blockIdx.x * ROWS + t;
    const float4* __restrict__ qr = (const float4*)(Q + b * (long long)NH);

    float p[NK];
    float rs = 0.f;
#pragma unroll
    for (int k4 = 0; k4 < NK / 4; ++k4) {
        float4 v = qr[k4];
        float p0 = v.x * v.x * s_ic[4 * k4 + 0];
        float p1 = v.y * v.y * s_ic[4 * k4 + 1];
        float p2 = v.z * v.z * s_ic[4 * k4 + 2];
        float p3 = v.w * v.w * s_ic[4 * k4 + 3];
        p[4 * k4 + 0] = p0;
        p[4 * k4 + 1] = p1;
        p[4 * k4 + 2] = p2;
        p[4 * k4 + 3] = p3;
        rs += (p0 + p1) + (p2 + p3);
    }
    const float inv = 1.f / rs;

    float4* __restrict__ po = (float4*)(P + b * (long long)NH);
#pragma unroll
    for (int k4 = 0; k4 < NK / 4; ++k4) {
        float4 v;
        v.x = p[4 * k4 + 0] * inv;
        v.y = p[4 * k4 + 1] * inv;
        v.z = p[4 * k4 + 2] * inv;
        v.w = p[4 * k4 + 3] * inv;
        po[k4] = v;
    }
}

// ---------------------------------------------------------------------------
extern "C" void kernel_launch(void* const* d_in, const int* in_sizes, int n_in,
                              void* d_out, int out_size) {
    const float* z = (const float*)d_in[0];        // (BS, 64)
    const float* c = (const float*)d_in[1];        // (64, 64)
    const long long n_rows = (long long)in_sizes[0] / NH;

    float* Q = (float*)d_out;                      // (BS, 64)
    float* P = Q + n_rows * NK;                    // (BS, 64)

    const int grid = (int)(n_rows / ROWS);

    k_pre<<<1, 64>>>(c);
    k_pass1<<<grid, ROWS>>>(z, c, Q);
    k_pass2<<<grid, ROWS>>>(Q, P);
}

// round 2
// speedup vs baseline: 1.5231x; 1.5231x over previous
#include <cuda_runtime.h>
#include <cstdint>

// BS=1048576, N_HIDDEN=64, N_CLUSTERS=64, ALPHA=1
#define NH 64
#define NK 64
#define THREADS 256
#define RPB 256          // rows per block (2 rows per thread, 2 threads per row)

__device__ float g_c2[NK];
__device__ float g_colsum[NK];

// ---------------------------------------------------------------------------
// K0: ||c_k||^2 + zero colsum accumulator (re-zeroed every launch: graph-safe)
// ---------------------------------------------------------------------------
__global__ void k_pre(const float* __restrict__ c) {
    int k = threadIdx.x;
    if (k < NK) {
        const float4* cr = (const float4*)(c + k * NH);
        float s = 0.f;
#pragma unroll
        for (int i = 0; i < NH / 4; ++i) {
            float4 v = cr[i];
            s = fmaf(v.x, v.x, s);
            s = fmaf(v.y, v.y, s);
            s = fmaf(v.z, v.z, s);
            s = fmaf(v.w, v.w, s);
        }
        g_c2[k] = s;
        g_colsum[k] = 0.f;
    }
}

#define FMA2(acc, a, b) \
    asm("fma.rn.f32x2 %0, %1, %2, %0;" : "+l"(acc) : "l"(a), "l"(b))
#define PACK2(dst, lo, hi) \
    asm("mov.b64 %0, {%1, %2};" : "=l"(dst) : "f"(lo), "f"(hi))
#define UNPACK2(lo, hi, src) \
    asm("mov.b64 {%0, %1}, %2;" : "=f"(lo), "=f"(hi) : "l"(src))

// ---------------------------------------------------------------------------
// K1: Q pass. Each thread: 2 rows x 32 clusters (thread pair t, t^1 covers the
// full 64 clusters of the same 2 rows). Centroids transposed in shared, split
// into two arrays offset by 64B so the two per-parity broadcast addresses hit
// disjoint bank groups (conflict-free).
// ---------------------------------------------------------------------------
__global__ void __launch_bounds__(THREADS, 2)
k_pass1(const float* __restrict__ z, const float* __restrict__ c,
        float* __restrict__ Q) {
    // cs layout: [csA: 64h x 32k][16-float pad][csB: 64h x 32k]
    __shared__ __align__(16) float cs[2 * NH * 32 + 16];
    __shared__ float s_c2[NK];
    __shared__ float s_col[NK];

    const int t = threadIdx.x;
    constexpr int CSB = NH * 32 + 16;  // csB offset (bank group +16)

    // Transpose centroids into shared.
    for (int i = t; i < NK * NH; i += THREADS) {
        int k = i >> 6;
        int h = i & 63;
        float v = c[i];
        if (k < 32)
            cs[h * 32 + k] = v;
        else
            cs[CSB + h * 32 + (k - 32)] = v;
    }
    if (t < NK) {
        s_c2[t] = g_c2[t];
        s_col[t] = 0.f;
    }
    __syncthreads();

    const int khalf = t & 1;
    const long long r0 = (long long)blockIdx.x * RPB + ((t >> 1) << 1);
    const float4* __restrict__ zr0 = (const float4*)(z + r0 * NH);
    const float4* __restrict__ zr1 = (const float4*)(z + (r0 + 1) * NH);
    const float* __restrict__ cbase = cs + khalf * CSB;

    unsigned long long acc0[16], acc1[16];
#pragma unroll
    for (int i = 0; i < 16; ++i) {
        acc0[i] = 0ULL;
        acc1[i] = 0ULL;
    }
    unsigned long long z2p = 0ULL;  // packed (z2_row0, z2_row1)

#pragma unroll 4
    for (int h4 = 0; h4 < NH / 4; ++h4) {
        float4 za = zr0[h4];
        float4 zb = zr1[h4];
        float a[4] = {za.x, za.y, za.z, za.w};
        float b[4] = {zb.x, zb.y, zb.z, zb.w};
#pragma unroll
        for (int j = 0; j < 4; ++j) {
            unsigned long long zz0, zz1, zzp;
            PACK2(zz0, a[j], a[j]);
            PACK2(zz1, b[j], b[j]);
            PACK2(zzp, a[j], b[j]);
            FMA2(z2p, zzp, zzp);
            const ulonglong2* __restrict__ cp =
                (const ulonglong2*)(cbase + (h4 * 4 + j) * 32);
#pragma unroll
            for (int kk = 0; kk < 8; ++kk) {
                ulonglong2 cv = cp[kk];  // broadcast LDS.128
                FMA2(acc0[2 * kk], zz0, cv.x);
                FMA2(acc0[2 * kk + 1], zz0, cv.y);
                FMA2(acc1[2 * kk], zz1, cv.x);
                FMA2(acc1[2 * kk + 1], zz1, cv.y);
            }
        }
    }

    float z2_0, z2_1;
    UNPACK2(z2_0, z2_1, z2p);

    const float* __restrict__ myc2 = s_c2 + khalf * 32;

    // ---- row 0 epilogue ----
    float q0[32], q1[32];
    float rs0 = 0.f, rs1 = 0.f;
#pragma unroll
    for (int i = 0; i < 16; ++i) {
        float d0, d1;
        UNPACK2(d0, d1, acc0[i]);
        float da = fmaf(-2.f, d0, z2_0 + myc2[2 * i]);
        float db = fmaf(-2.f, d1, z2_0 + myc2[2 * i + 1]);
        float sa = __fsqrt_rn(fmaxf(da, 0.f));
        float sb = __fsqrt_rn(fmaxf(db, 0.f));
        float qa = __fdividef(1.f, 1.f + sa);
        float qb = __fdividef(1.f, 1.f + sb);
        q0[2 * i] = qa;
        q0[2 * i + 1] = qb;
        rs0 += qa + qb;
    }
#pragma unroll
    for (int i = 0; i < 16; ++i) {
        float d0, d1;
        UNPACK2(d0, d1, acc1[i]);
        float da = fmaf(-2.f, d0, z2_1 + myc2[2 * i]);
        float db = fmaf(-2.f, d1, z2_1 + myc2[2 * i + 1]);
        float sa = __fsqrt_rn(fmaxf(da, 0.f));
        float sb = __fsqrt_rn(fmaxf(db, 0.f));
        float qa = __fdividef(1.f, 1.f + sa);
        float qb = __fdividef(1.f, 1.f + sb);
        q1[2 * i] = qa;
        q1[2 * i + 1] = qb;
        rs1 += qa + qb;
    }

    // Combine row sums across the thread pair (t ^ 1 owns the other 32 cols).
    rs0 += __shfl_xor_sync(0xffffffffu, rs0, 1);
    rs1 += __shfl_xor_sync(0xffffffffu, rs1, 1);
    const float inv0 = __fdividef(1.f, rs0);
    const float inv1 = __fdividef(1.f, rs1);

#pragma unroll
    for (int k = 0; k < 32; ++k) {
        q0[k] *= inv0;
        q1[k] *= inv1;
    }

    // Store normalized half-rows (128B contiguous per thread).
    float4* __restrict__ qo0 = (float4*)(Q + r0 * NH + khalf * 32);
    float4* __restrict__ qo1 = (float4*)(Q + (r0 + 1) * NH + khalf * 32);
#pragma unroll
    for (int k4 = 0; k4 < 8; ++k4) {
        float4 v0, v1;
        v0.x = q0[4 * k4];     v0.y = q0[4 * k4 + 1];
        v0.z = q0[4 * k4 + 2]; v0.w = q0[4 * k4 + 3];
        v1.x = q1[4 * k4];     v1.y = q1[4 * k4 + 1];
        v1.z = q1[4 * k4 + 2]; v1.w = q1[4 * k4 + 3];
        qo0[k4] = v0;
        qo1[k4] = v1;
    }

    // Column sums: reduce across lanes of the same parity (offsets 2..16),
    // lanes 0/1 write 32 partials each to shared, then one global atomic/col.
#pragma unroll
    for (int k = 0; k < 32; ++k) {
        float v = q0[k] + q1[k];
        v += __shfl_xor_sync(0xffffffffu, v, 2);
        v += __shfl_xor_sync(0xffffffffu, v, 4);
        v += __shfl_xor_sync(0xffffffffu, v, 8);
        v += __shfl_xor_sync(0xffffffffu, v, 16);
        if ((t & 31) < 2) atomicAdd(&s_col[khalf * 32 + k], v);
    }
    __syncthreads();
    if (t < NK) atomicAdd(&g_colsum[t], s_col[t]);
}

// ---------------------------------------------------------------------------
// K2: P = rownorm(Q^2 / colsum). Streaming pass, one row per thread.
// ---------------------------------------------------------------------------
__global__ void __launch_bounds__(THREADS, 2)
k_pass2(const float* __restrict__ Q, float* __restrict__ P) {
    __shared__ float s_ic[NK];
    const int t = threadIdx.x;
    if (t < NK) s_ic[t] = __fdividef(1.f, g_colsum[t]);
    __syncthreads();

    const long long b = (long long)blockIdx.x * THREADS + t;
    const float4* __restrict__ qr = (const float4*)(Q + b * (long long)NH);

    float p[NK];
    float rs = 0.f;
#pragma unroll
    for (int k4 = 0; k4 < NK / 4; ++k4) {
        float4 v = qr[k4];
        float p0 = v.x * v.x * s_ic[4 * k4 + 0];
        float p1 = v.y * v.y * s_ic[4 * k4 + 1];
        float p2 = v.z * v.z * s_ic[4 * k4 + 2];
        float p3 = v.w * v.w * s_ic[4 * k4 + 3];
        p[4 * k4 + 0] = p0;
        p[4 * k4 + 1] = p1;
        p[4 * k4 + 2] = p2;
        p[4 * k4 + 3] = p3;
        rs += (p0 + p1) + (p2 + p3);
    }
    const float inv = __fdividef(1.f, rs);

    float4* __restrict__ po = (float4*)(P + b * (long long)NH);
#pragma unroll
    for (int k4 = 0; k4 < NK / 4; ++k4) {
        float4 v;
        v.x = p[4 * k4 + 0] * inv;
        v.y = p[4 * k4 + 1] * inv;
        v.z = p[4 * k4 + 2] * inv;
        v.w = p[4 * k4 + 3] * inv;
        po[k4] = v;
    }
}

// ---------------------------------------------------------------------------
extern "C" void kernel_launch(void* const* d_in, const int* in_sizes, int n_in,
                              void* d_out, int out_size) {
    const float* z = (const float*)d_in[0];  // (BS, 64)
    const float* c = (const float*)d_in[1];  // (64, 64)
    const long long n_rows = (long long)in_sizes[0] / NH;

    float* Q = (float*)d_out;
    float* P = Q + n_rows * NK;

    k_pre<<<1, 64>>>(c);
    k_pass1<<<(int)(n_rows / RPB), THREADS>>>(z, c, Q);
    k_pass2<<<(int)(n_rows / THREADS), THREADS>>>(Q, P);
}

// round 4
// speedup vs baseline: 3.0251x; 1.9862x over previous
#include <cuda_runtime.h>
#include <cstdint>

#define NH 64
#define NK 64
#define TM 128          // rows per CTA (pass1)
#define P1T 128
#define P2T 256
#define STRD 68         // smem row stride in floats (conflict-free fragments)

// dynamic smem offsets (floats)
#define F_A    0                      // 128 x 68
#define F_B    (F_A + TM * STRD)      // 64 x 68
#define F_Z2   (F_B + NK * STRD)      // 128
#define F_C2   (F_Z2 + TM)            // 64
#define F_COL  (F_C2 + NK)            // 64
#define SMEM_FLOATS (F_COL + NK)
#define SMEM_BYTES  (SMEM_FLOATS * 4) // 53248

__device__ float g_colsum[NK];
__device__ unsigned g_done;

__device__ __forceinline__ uint32_t smem_u32(const void* p) {
    uint32_t a;
    asm("{ .reg .u64 t; cvta.to.shared.u64 t, %1; cvt.u32.u64 %0, t; }"
        : "=r"(a) : "l"(p));
    return a;
}
#define CP_ASYNC16(dst, src) \
    asm volatile("cp.async.cg.shared.global [%0], [%1], 16;" :: "r"(dst), "l"(src))

__device__ __forceinline__ void mma_tf32(float* d, uint32_t a0, uint32_t a1,
                                         uint32_t a2, uint32_t a3,
                                         uint32_t b0, uint32_t b1) {
    asm volatile(
        "mma.sync.aligned.m16n8k8.row.col.f32.tf32.tf32.f32 "
        "{%0,%1,%2,%3}, {%4,%5,%6,%7}, {%8,%9}, {%0,%1,%2,%3};"
        : "+f"(d[0]), "+f"(d[1]), "+f"(d[2]), "+f"(d[3])
        : "r"(a0), "r"(a1), "r"(a2), "r"(a3), "r"(b0), "r"(b1));
}
__device__ __forceinline__ float sqrt_ap(float x) {
    float r; asm("sqrt.approx.f32 %0, %1;" : "=f"(r) : "f"(x)); return r;
}
__device__ __forceinline__ float rcp_ap(float x) {
    float r; asm("rcp.approx.f32 %0, %1;" : "=f"(r) : "f"(x)); return r;
}

// ---------------------------------------------------------------------------
// Pass 1: Q = rownorm(1/(1+sqrt(max(||z||^2+||c||^2-2 z.c, 0)))) via tf32
// mma.sync; also accumulates column sums of normalized Q into g_colsum.
// ---------------------------------------------------------------------------
__global__ void __launch_bounds__(P1T, 4)
k_pass1(const float* __restrict__ z, const float* __restrict__ c,
        float* __restrict__ Q) {
    extern __shared__ __align__(16) float sm[];
    const uint32_t sb = smem_u32(sm);
    const int t = threadIdx.x;
    const int warp = t >> 5, lane = t & 31;
    const int g = lane >> 2, tig = lane & 3;

    const long long row0 = (long long)blockIdx.x * TM;

    // Stage z tile (128x64) and centroids (64x64) into stride-68 smem rows.
    {
        const char* zg = (const char*)(z + row0 * NH);
#pragma unroll 4
        for (int i = t; i < TM * 16; i += P1T) {
            int r = i >> 4, c4 = i & 15;
            CP_ASYNC16(sb + (F_A + r * STRD + c4 * 4) * 4, zg + (size_t)i * 16);
        }
#pragma unroll 2
        for (int i = t; i < NK * 16; i += P1T) {
            int r = i >> 4, c4 = i & 15;
            CP_ASYNC16(sb + (F_B + r * STRD + c4 * 4) * 4,
                       ((const char*)c) + (size_t)i * 16);
        }
        asm volatile("cp.async.commit_group;" ::: "memory");
    }
    if (t < NK) sm[F_COL + t] = 0.f;
    asm volatile("cp.async.wait_group 0;" ::: "memory");
    __syncthreads();

    // ||z_r||^2 (one row per thread) and ||c_n||^2 (t < 64).
    {
        float s = 0.f;
        const float4* ar = (const float4*)(sm + F_A + t * STRD);
#pragma unroll
        for (int j = 0; j < 16; ++j) {
            float4 v = ar[j];
            s = fmaf(v.x, v.x, s); s = fmaf(v.y, v.y, s);
            s = fmaf(v.z, v.z, s); s = fmaf(v.w, v.w, s);
        }
        sm[F_Z2 + t] = s;
        if (t < NK) {
            float sc = 0.f;
            const float4* br = (const float4*)(sm + F_B + t * STRD);
#pragma unroll
            for (int j = 0; j < 16; ++j) {
                float4 v = br[j];
                sc = fmaf(v.x, v.x, sc); sc = fmaf(v.y, v.y, sc);
                sc = fmaf(v.z, v.z, sc); sc = fmaf(v.w, v.w, sc);
            }
            sm[F_C2 + t] = sc;
        }
    }
    __syncthreads();

    // Main GEMM: warp w owns rows [w*32, w*32+32); 2 M-tiles x 8 N-tiles.
    float d[8][2][4];
#pragma unroll
    for (int nt = 0; nt < 8; ++nt)
#pragma unroll
        for (int mt = 0; mt < 2; ++mt)
#pragma unroll
            for (int j = 0; j < 4; ++j) d[nt][mt][j] = 0.f;

    const int rowbase = warp * 32;
    const uint32_t* sA = (const uint32_t*)sm + F_A;
    const uint32_t* sB = (const uint32_t*)sm + F_B;

#pragma unroll
    for (int ks = 0; ks < 8; ++ks) {
        uint32_t a[2][4];
#pragma unroll
        for (int mt = 0; mt < 2; ++mt) {
            const uint32_t* p =
                sA + (rowbase + mt * 16 + g) * STRD + ks * 8 + tig;
            a[mt][0] = p[0];
            a[mt][1] = p[8 * STRD];
            a[mt][2] = p[4];
            a[mt][3] = p[8 * STRD + 4];
        }
        uint32_t b[8][2];
#pragma unroll
        for (int nt = 0; nt < 8; ++nt) {
            const uint32_t* p = sB + (nt * 8 + g) * STRD + ks * 8 + tig;
            b[nt][0] = p[0];
            b[nt][1] = p[4];
        }
#pragma unroll
        for (int nt = 0; nt < 8; ++nt)
#pragma unroll
            for (int mt = 0; mt < 2; ++mt)
                mma_tf32(d[nt][mt], a[mt][0], a[mt][1], a[mt][2], a[mt][3],
                         b[nt][0], b[nt][1]);
    }

    // Epilogue. Thread owns rows {g, g+8, g+16, g+24}+rowbase, cols
    // nt*8 + 2*tig + {0,1}. d[nt][mt][0,1]=low row, [2,3]=high row.
    float z2r[4];
    z2r[0] = sm[F_Z2 + rowbase + g];
    z2r[1] = sm[F_Z2 + rowbase + g + 8];
    z2r[2] = sm[F_Z2 + rowbase + g + 16];
    z2r[3] = sm[F_Z2 + rowbase + g + 24];

    float q[4][16];  // [row][nt*2 + j]
    float rs[4] = {0.f, 0.f, 0.f, 0.f};
#pragma unroll
    for (int nt = 0; nt < 8; ++nt) {
        float c2a = sm[F_C2 + nt * 8 + 2 * tig];
        float c2b = sm[F_C2 + nt * 8 + 2 * tig + 1];
#pragma unroll
        for (int mt = 0; mt < 2; ++mt) {
#pragma unroll
            for (int hr = 0; hr < 2; ++hr) {
                int r = mt * 2 + hr;
                float da = fmaf(-2.f, d[nt][mt][hr * 2],     z2r[r] + c2a);
                float db = fmaf(-2.f, d[nt][mt][hr * 2 + 1], z2r[r] + c2b);
                float qa = rcp_ap(1.f + sqrt_ap(fmaxf(da, 0.f)));
                float qb = rcp_ap(1.f + sqrt_ap(fmaxf(db, 0.f)));
                q[r][nt * 2]     = qa;
                q[r][nt * 2 + 1] = qb;
                rs[r] += qa + qb;
            }
        }
    }
    // Row sums complete across the tig group (lanes sharing the same rows).
#pragma unroll
    for (int r = 0; r < 4; ++r) {
        rs[r] += __shfl_xor_sync(0xffffffffu, rs[r], 1);
        rs[r] += __shfl_xor_sync(0xffffffffu, rs[r], 2);
        rs[r] = rcp_ap(rs[r]);
    }

    // Normalize, store Q (float2 per (row, nt): full 32B sectors), colsum.
    float cs[16];
#pragma unroll
    for (int i = 0; i < 16; ++i) cs[i] = 0.f;

    const int rloc[4] = {rowbase + g, rowbase + g + 8, rowbase + g + 16,
                         rowbase + g + 24};
#pragma unroll
    for (int r = 0; r < 4; ++r) {
        float* outr = Q + (row0 + rloc[r]) * NH + 2 * tig;
#pragma unroll
        for (int nt = 0; nt < 8; ++nt) {
            float qa = q[r][nt * 2] * rs[r];
            float qb = q[r][nt * 2 + 1] * rs[r];
            cs[nt * 2] += qa;
            cs[nt * 2 + 1] += qb;
            float2 v = {qa, qb};
            *(float2*)(outr + nt * 8) = v;
        }
    }
    // Column sums across the g group (lanes covering the same cols).
#pragma unroll
    for (int i = 0; i < 16; ++i) {
        cs[i] += __shfl_xor_sync(0xffffffffu, cs[i], 4);
        cs[i] += __shfl_xor_sync(0xffffffffu, cs[i], 8);
        cs[i] += __shfl_xor_sync(0xffffffffu, cs[i], 16);
    }
    if (g == 0) {
#pragma unroll
        for (int nt = 0; nt < 8; ++nt) {
            atomicAdd(&sm[F_COL + nt * 8 + 2 * tig], cs[nt * 2]);
            atomicAdd(&sm[F_COL + nt * 8 + 2 * tig + 1], cs[nt * 2 + 1]);
        }
    }
    __syncthreads();
    if (t < NK) atomicAdd(&g_colsum[t], sm[F_COL + t]);
}

// ---------------------------------------------------------------------------
// Pass 2: P = rownorm(Q^2 / colsum). Last block re-zeroes colsum/ticket so
// every graph replay starts from a clean state.
// ---------------------------------------------------------------------------
__global__ void __launch_bounds__(P2T)
k_pass2(const float* __restrict__ Q, float* __restrict__ P) {
    __shared__ float s_ic[NK];
    const int t = threadIdx.x;
    if (t < NK) s_ic[t] = rcp_ap(g_colsum[t]);
    __syncthreads();

    if (t == 0) {
        unsigned old = atomicAdd(&g_done, 1u);
        if (old == gridDim.x - 1) {
#pragma unroll
            for (int k = 0; k < NK; ++k) g_colsum[k] = 0.f;
            g_done = 0;
            __threadfence();
        }
    }

    const long long b = (long long)blockIdx.x * P2T + t;
    const float4* __restrict__ qr = (const float4*)(Q + b * (long long)NH);

    float p[NK];
    float rsum = 0.f;
#pragma unroll
    for (int k4 = 0; k4 < NK / 4; ++k4) {
        float4 v = qr[k4];
        float p0 = v.x * v.x * s_ic[4 * k4 + 0];
        float p1 = v.y * v.y * s_ic[4 * k4 + 1];
        float p2 = v.z * v.z * s_ic[4 * k4 + 2];
        float p3 = v.w * v.w * s_ic[4 * k4 + 3];
        p[4 * k4 + 0] = p0; p[4 * k4 + 1] = p1;
        p[4 * k4 + 2] = p2; p[4 * k4 + 3] = p3;
        rsum += (p0 + p1) + (p2 + p3);
    }
    const float inv = rcp_ap(rsum);

    float4* __restrict__ po = (float4*)(P + b * (long long)NH);
#pragma unroll
    for (int k4 = 0; k4 < NK / 4; ++k4) {
        float4 v;
        v.x = p[4 * k4 + 0] * inv;
        v.y = p[4 * k4 + 1] * inv;
        v.z = p[4 * k4 + 2] * inv;
        v.w = p[4 * k4 + 3] * inv;
        po[k4] = v;
    }
}

// ---------------------------------------------------------------------------
extern "C" void kernel_launch(void* const* d_in, const int* in_sizes, int n_in,
                              void* d_out, int out_size) {
    const float* z = (const float*)d_in[0];  // (BS, 64)
    const float* c = (const float*)d_in[1];  // (64, 64)
    const long long n_rows = (long long)in_sizes[0] / NH;

    float* Q = (float*)d_out;
    float* P = Q + n_rows * NK;

    static bool attr_set = false;
    if (!attr_set) {
        cudaFuncSetAttribute(k_pass1, cudaFuncAttributeMaxDynamicSharedMemorySize,
                             SMEM_BYTES);
        attr_set = true;
    }

    k_pass1<<<(int)(n_rows / TM), P1T, SMEM_BYTES>>>(z, c, Q);
    k_pass2<<<(int)(n_rows / P2T), P2T>>>(Q, P);
}

// round 5
// speedup vs baseline: 3.2234x; 1.0656x over previous
#include <cuda_runtime.h>
#include <cstdint>

#define NH 64
#define NK 64
#define TM 128          // rows per CTA (pass1)
#define P1T 256
#define P2T 256
#define STRD 68         // smem row stride in floats (conflict-free fragments)

// dynamic smem offsets (floats)
#define F_A    0                      // 128 x 68
#define F_B    (F_A + TM * STRD)      // 64 x 68
#define F_Z2   (F_B + NK * STRD)      // 128
#define F_C2   (F_Z2 + TM)            // 64
#define F_COL  (F_C2 + NK)            // 64
#define SMEM_FLOATS (F_COL + NK)
#define SMEM_BYTES  (SMEM_FLOATS * 4) // 53248

__device__ float g_colsum[NK];
__device__ unsigned g_done;

__device__ __forceinline__ uint32_t smem_u32(const void* p) {
    uint32_t a;
    asm("{ .reg .u64 t; cvta.to.shared.u64 t, %1; cvt.u32.u64 %0, t; }"
        : "=r"(a) : "l"(p));
    return a;
}
#define CP_ASYNC16(dst, src) \
    asm volatile("cp.async.cg.shared.global [%0], [%1], 16;" :: "r"(dst), "l"(src))

__device__ __forceinline__ void mma_tf32(float* d, uint32_t a0, uint32_t a1,
                                         uint32_t a2, uint32_t a3,
                                         uint32_t b0, uint32_t b1) {
    asm volatile(
        "mma.sync.aligned.m16n8k8.row.col.f32.tf32.tf32.f32 "
        "{%0,%1,%2,%3}, {%4,%5,%6,%7}, {%8,%9}, {%0,%1,%2,%3};"
        : "+f"(d[0]), "+f"(d[1]), "+f"(d[2]), "+f"(d[3])
        : "r"(a0), "r"(a1), "r"(a2), "r"(a3), "r"(b0), "r"(b1));
}
__device__ __forceinline__ float sqrt_ap(float x) {
    float r; asm("sqrt.approx.f32 %0, %1;" : "=f"(r) : "f"(x)); return r;
}
__device__ __forceinline__ float rcp_ap(float x) {
    float r; asm("rcp.approx.f32 %0, %1;" : "=f"(r) : "f"(x)); return r;
}

// ---------------------------------------------------------------------------
// Pass 1: Q = rownorm(1/(1+sqrt(max(||z||^2+||c||^2-2 z.c, 0)))) via tf32
// mma.sync. 8 warps x (16 rows x 64 cols) per CTA. Also accumulates column
// sums of normalized Q into g_colsum.
// ---------------------------------------------------------------------------
__global__ void __launch_bounds__(P1T, 3)
k_pass1(const float* __restrict__ z, const float* __restrict__ c,
        float* __restrict__ Q) {
    extern __shared__ __align__(16) float sm[];
    const uint32_t sb = smem_u32(sm);
    const int t = threadIdx.x;
    const int warp = t >> 5, lane = t & 31;
    const int g = lane >> 2, tig = lane & 3;

    const long long row0 = (long long)blockIdx.x * TM;

    // Stage z tile (128x64) and centroids (64x64) into stride-68 smem rows.
    {
        const char* zg = (const char*)(z + row0 * NH);
#pragma unroll 8
        for (int i = t; i < TM * 16; i += P1T) {
            int r = i >> 4, c4 = i & 15;
            CP_ASYNC16(sb + (F_A + r * STRD + c4 * 4) * 4, zg + (size_t)i * 16);
        }
#pragma unroll 4
        for (int i = t; i < NK * 16; i += P1T) {
            int r = i >> 4, c4 = i & 15;
            CP_ASYNC16(sb + (F_B + r * STRD + c4 * 4) * 4,
                       ((const char*)c) + (size_t)i * 16);
        }
        asm volatile("cp.async.commit_group;" ::: "memory");
    }
    if (t < NK) sm[F_COL + t] = 0.f;
    asm volatile("cp.async.wait_group 0;" ::: "memory");
    __syncthreads();

    // ||z_r||^2 (threads 0..127) and ||c_n||^2 (threads 128..191).
    if (t < TM) {
        float s = 0.f;
        const float4* ar = (const float4*)(sm + F_A + t * STRD);
#pragma unroll
        for (int j = 0; j < 16; ++j) {
            float4 v = ar[j];
            s = fmaf(v.x, v.x, s); s = fmaf(v.y, v.y, s);
            s = fmaf(v.z, v.z, s); s = fmaf(v.w, v.w, s);
        }
        sm[F_Z2 + t] = s;
    } else if (t < TM + NK) {
        float sc = 0.f;
        const float4* br = (const float4*)(sm + F_B + (t - TM) * STRD);
#pragma unroll
        for (int j = 0; j < 16; ++j) {
            float4 v = br[j];
            sc = fmaf(v.x, v.x, sc); sc = fmaf(v.y, v.y, sc);
            sc = fmaf(v.z, v.z, sc); sc = fmaf(v.w, v.w, sc);
        }
        sm[F_C2 + (t - TM)] = sc;
    }
    __syncthreads();

    // GEMM: warp w owns rows [w*16, w*16+16); 8 N-tiles of 8 cols.
    float d[8][4];
#pragma unroll
    for (int nt = 0; nt < 8; ++nt)
#pragma unroll
        for (int j = 0; j < 4; ++j) d[nt][j] = 0.f;

    const int rowbase = warp * 16;
    const uint32_t* sA = (const uint32_t*)sm + F_A;
    const uint32_t* sB = (const uint32_t*)sm + F_B;

#pragma unroll
    for (int ks = 0; ks < 8; ++ks) {
        const uint32_t* pa = sA + (rowbase + g) * STRD + ks * 8 + tig;
        uint32_t a0 = pa[0];
        uint32_t a1 = pa[8 * STRD];
        uint32_t a2 = pa[4];
        uint32_t a3 = pa[8 * STRD + 4];
        uint32_t b[8][2];
#pragma unroll
        for (int nt = 0; nt < 8; ++nt) {
            const uint32_t* pb = sB + (nt * 8 + g) * STRD + ks * 8 + tig;
            b[nt][0] = pb[0];
            b[nt][1] = pb[4];
        }
#pragma unroll
        for (int nt = 0; nt < 8; ++nt)
            mma_tf32(d[nt], a0, a1, a2, a3, b[nt][0], b[nt][1]);
    }

    // Epilogue: thread owns rows r0=rowbase+g, r1=rowbase+g+8,
    // cols nt*8 + 2*tig + {0,1}. d[nt][0,1]=row r0, d[nt][2,3]=row r1.
    const float z2a = sm[F_Z2 + rowbase + g];
    const float z2b = sm[F_Z2 + rowbase + g + 8];

    float q0[16], q1[16];
    float rs0 = 0.f, rs1 = 0.f;
#pragma unroll
    for (int nt = 0; nt < 8; ++nt) {
        float c2a = sm[F_C2 + nt * 8 + 2 * tig];
        float c2b = sm[F_C2 + nt * 8 + 2 * tig + 1];
        float d2;
        d2 = fmaf(-2.f, d[nt][0], z2a + c2a);
        float qa0 = rcp_ap(1.f + sqrt_ap(fmaxf(d2, 0.f)));
        d2 = fmaf(-2.f, d[nt][1], z2a + c2b);
        float qa1 = rcp_ap(1.f + sqrt_ap(fmaxf(d2, 0.f)));
        d2 = fmaf(-2.f, d[nt][2], z2b + c2a);
        float qb0 = rcp_ap(1.f + sqrt_ap(fmaxf(d2, 0.f)));
        d2 = fmaf(-2.f, d[nt][3], z2b + c2b);
        float qb1 = rcp_ap(1.f + sqrt_ap(fmaxf(d2, 0.f)));
        q0[nt * 2] = qa0; q0[nt * 2 + 1] = qa1;
        q1[nt * 2] = qb0; q1[nt * 2 + 1] = qb1;
        rs0 += qa0 + qa1;
        rs1 += qb0 + qb1;
    }
    // Complete row sums across the tig group.
    rs0 += __shfl_xor_sync(0xffffffffu, rs0, 1);
    rs0 += __shfl_xor_sync(0xffffffffu, rs0, 2);
    rs1 += __shfl_xor_sync(0xffffffffu, rs1, 1);
    rs1 += __shfl_xor_sync(0xffffffffu, rs1, 2);
    rs0 = rcp_ap(rs0);
    rs1 = rcp_ap(rs1);

    // Normalize + store Q (float2 = full 32B sectors across tig group),
    // accumulating per-col sums (both rows) in place.
    {
        float* o0 = Q + (row0 + rowbase + g) * NH + 2 * tig;
        float* o1 = Q + (row0 + rowbase + g + 8) * NH + 2 * tig;
#pragma unroll
        for (int nt = 0; nt < 8; ++nt) {
            float a0 = q0[nt * 2] * rs0, a1 = q0[nt * 2 + 1] * rs0;
            float b0 = q1[nt * 2] * rs1, b1 = q1[nt * 2 + 1] * rs1;
            float2 va = {a0, a1}, vb = {b0, b1};
            *(float2*)(o0 + nt * 8) = va;
            *(float2*)(o1 + nt * 8) = vb;
            q0[nt * 2] = a0 + b0;        // reuse as colsum partial
            q0[nt * 2 + 1] = a1 + b1;
        }
    }
    // Column sums across the g group (8 rows each -> whole warp's 16 rows).
#pragma unroll
    for (int i = 0; i < 16; ++i) {
        q0[i] += __shfl_xor_sync(0xffffffffu, q0[i], 4);
        q0[i] += __shfl_xor_sync(0xffffffffu, q0[i], 8);
        q0[i] += __shfl_xor_sync(0xffffffffu, q0[i], 16);
    }
    if (g == 0) {
#pragma unroll
        for (int nt = 0; nt < 8; ++nt) {
            atomicAdd(&sm[F_COL + nt * 8 + 2 * tig], q0[nt * 2]);
            atomicAdd(&sm[F_COL + nt * 8 + 2 * tig + 1], q0[nt * 2 + 1]);
        }
    }
    __syncthreads();
    if (t < NK) atomicAdd(&g_colsum[t], sm[F_COL + t]);
}

// ---------------------------------------------------------------------------
// Pass 2: P = rownorm(Q^2 / colsum). Quarter-row (16 floats) per thread for
// high occupancy; rowsum completed via shfl. Last block re-zeroes colsum and
// the ticket so every graph replay starts clean.
// ---------------------------------------------------------------------------
__global__ void __launch_bounds__(P2T)
k_pass2(const float* __restrict__ Q, float* __restrict__ P) {
    __shared__ float s_ic[NK];
    const int t = threadIdx.x;
    if (t < NK) s_ic[t] = rcp_ap(g_colsum[t]);
    __syncthreads();

    if (t == 0) {
        unsigned old = atomicAdd(&g_done, 1u);
        if (old == gridDim.x - 1) {
#pragma unroll
            for (int k = 0; k < NK; ++k) g_colsum[k] = 0.f;
            g_done = 0;
            __threadfence();
        }
    }

    const long long row = (long long)blockIdx.x * (P2T / 4) + (t >> 2);
    const int qpart = t & 3;
    const float4* __restrict__ qr =
        (const float4*)(Q + row * NH + qpart * 16);
    const float* ic = s_ic + qpart * 16;

    float p[16];
    float rs = 0.f;
#pragma unroll
    for (int j = 0; j < 4; ++j) {
        float4 v = qr[j];
        float p0 = v.x * v.x * ic[4 * j + 0];
        float p1 = v.y * v.y * ic[4 * j + 1];
        float p2 = v.z * v.z * ic[4 * j + 2];
        float p3 = v.w * v.w * ic[4 * j + 3];
        p[4 * j + 0] = p0; p[4 * j + 1] = p1;
        p[4 * j + 2] = p2; p[4 * j + 3] = p3;
        rs += (p0 + p1) + (p2 + p3);
    }
    rs += __shfl_xor_sync(0xffffffffu, rs, 1);
    rs += __shfl_xor_sync(0xffffffffu, rs, 2);
    const float inv = rcp_ap(rs);

    float4* __restrict__ po = (float4*)(P + row * NH + qpart * 16);
#pragma unroll
    for (int j = 0; j < 4; ++j) {
        float4 v;
        v.x = p[4 * j + 0] * inv;
        v.y = p[4 * j + 1] * inv;
        v.z = p[4 * j + 2] * inv;
        v.w = p[4 * j + 3] * inv;
        po[j] = v;
    }
}

// ---------------------------------------------------------------------------
extern "C" void kernel_launch(void* const* d_in, const int* in_sizes, int n_in,
                              void* d_out, int out_size) {
    const float* z = (const float*)d_in[0];  // (BS, 64)
    const float* c = (const float*)d_in[1];  // (64, 64)
    const long long n_rows = (long long)in_sizes[0] / NH;

    float* Q = (float*)d_out;
    float* P = Q + n_rows * NK;

    static bool attr_set = false;
    if (!attr_set) {
        cudaFuncSetAttribute(k_pass1, cudaFuncAttributeMaxDynamicSharedMemorySize,
                             SMEM_BYTES);
        attr_set = true;
    }

    k_pass1<<<(int)(n_rows / TM), P1T, SMEM_BYTES>>>(z, c, Q);
    k_pass2<<<(int)(n_rows / (P2T / 4)), P2T>>>(Q, P);
}